// round 11
// baseline (speedup 1.0000x reference)
#include <cuda_runtime.h>
#include <cstdint>
typedef unsigned long long ull;
typedef unsigned u32;
typedef unsigned short u16;

#define B   8
#define NC  2
#define NS  8
#define CH  64
#define H   192
#define WI  192
#define HW  (H*WI)
#define PP     37636
#define NTILES 589
#define PPK    (NTILES*64)
#define PLANE  (PPK + 512)
#define TPC    16

__device__ float d_g[B*NC*HW];
__device__ u32   d_snhl[B*16*PLANE];
__device__ float d_Z[B*NC*NS];
__device__ float d_S[B*16*576];
__device__ float d_tok2[B*NC*CH];
__device__ ull   d_M2[B*32*20];
__device__ float d_sum[CH];
__device__ float d_ss[CH];

__device__ __forceinline__ float sigm(float x){ return 1.f/(1.f+__expf(-x)); }
__device__ __forceinline__ void ffma2(ull& d, ull a, ull b){
    asm("fma.rn.f32x2 %0, %1, %2, %0;" : "+l"(d) : "l"(a), "l"(b));
}
__device__ __forceinline__ void fadd2(ull& d, ull a){
    asm("add.rn.f32x2 %0, %0, %1;" : "+l"(d) : "l"(a));
}
__device__ __forceinline__ ull pack2(float lo, float hi){
    ull r; asm("mov.b64 %0, {%1,%2};" : "=l"(r) : "f"(lo), "f"(hi)); return r;
}
__device__ __forceinline__ float lo2(ull v){ return __uint_as_float((unsigned)v); }
__device__ __forceinline__ float hi2(ull v){ return __uint_as_float((unsigned)(v>>32)); }
__device__ __forceinline__ u16 f2bf(float v){
    u16 r; asm("cvt.rn.bf16.f32 %0, %1;" : "=h"(r) : "f"(v)); return r;
}
__device__ __forceinline__ float bf2f(u16 u){
    float r; asm("cvt.f32.bf16 %0, %1;" : "=f"(r) : "h"(u)); return r;
}
__device__ __forceinline__ u32 smem_to_u32(const void* p){
    u32 a; asm("{ .reg .u64 t; cvta.to.shared.u64 t, %1; cvt.u32.u64 %0, t; }" : "=r"(a) : "l"(p)); return a;
}
#define SWZ(off) ((off) ^ (((off) >> 3) & 0x70))

// ---- warp-MMA helpers (baseline ISA: sm_75+/sm_80+, compile for plain sm_103) ----
__device__ __forceinline__ void ldm4(u32& r0, u32& r1, u32& r2, u32& r3, u32 addr){
    asm volatile("ldmatrix.sync.aligned.m8n8.x4.shared.b16 {%0,%1,%2,%3}, [%4];"
        : "=r"(r0),"=r"(r1),"=r"(r2),"=r"(r3) : "r"(addr));
}
__device__ __forceinline__ void mma_bf16(float (&c)[4], u32 a0,u32 a1,u32 a2,u32 a3, u32 b0,u32 b1){
    asm volatile("mma.sync.aligned.m16n8k16.row.col.f32.bf16.bf16.f32 "
        "{%0,%1,%2,%3}, {%4,%5,%6,%7}, {%8,%9}, {%0,%1,%2,%3};"
        : "+f"(c[0]),"+f"(c[1]),"+f"(c[2]),"+f"(c[3])
        : "r"(a0),"r"(a1),"r"(a2),"r"(a3),"r"(b0),"r"(b1));
}

// ---------------- K0a: zero d_S / d_Z ----------------
__global__ void k_zero() {
    int i = blockIdx.x*256 + threadIdx.x;   // 288*256 = 73728 exact = B*16*576
    d_S[i] = 0.f;
    if (i < B*NC*NS) d_Z[i] = 0.f;
}
// ---------------- K0b: zero tok2 / sums (3rd launch; makes k_S the profiled 4th) ----------------
__global__ void k_zero2() {
    int i = threadIdx.x;                    // 1024
    if (i < B*NC*CH) d_tok2[i] = 0.f;
    if (i < CH) { d_sum[i] = 0.f; d_ss[i] = 0.f; }
}

// ---------------- K1: padded split-bf16 space maps + Z + g ----------------
__global__ void k_pre(const float* __restrict__ score, const float* __restrict__ Wk,
                      const float* __restrict__ Wcv, const float* __restrict__ Wa,
                      const float* __restrict__ Wc) {
    __shared__ float wk[63], cw[8], aw[8];
    int tid = threadIdx.x;
    if (tid < 63) wk[tid] = Wk[tid];
    if (tid < 8) { cw[tid] = Wc[tid]*Wcv[tid]; aw[tid] = Wa[tid]; }
    __syncthreads();
    int bc = blockIdx.y;
    int q = blockIdx.x*256 + tid;           // 150*256 >= PLANE
    float val[8];
#pragma unroll
    for (int k = 0; k < 8; k++) val[k] = 0.f;
    bool inq = (q < PLANE);
    int p = q - 256;
    bool inimg = false; int h = 0, w = 0;
    if (inq && p >= 0 && p < PP) {
        int hp = p/194, wp = p - hp*194;
        if (hp >= 1 && hp <= 192 && wp >= 1 && wp <= 192) { inimg = true; h = hp-1; w = wp-1; }
    }
    if (inimg) {
        const float* sc = score + bc*HW;
        float win[9];
#pragma unroll
        for (int u = 0; u < 3; u++)
#pragma unroll
            for (int v = 0; v < 3; v++) {
                int hh = h+u-1, ww = w+v-1;
                win[u*3+v] = (hh>=0 && hh<H && ww>=0 && ww<WI) ? sigm(sc[hh*WI+ww]) : 0.f;
            }
        val[0] = win[4];
#pragma unroll
        for (int k = 0; k < 7; k++) {
            float a = 0.f;
#pragma unroll
            for (int j = 0; j < 9; j++) a += wk[k*9+j]*win[j];
            val[k+1] = sigm(a);
        }
        float g = 0.f;
#pragma unroll
        for (int s = 0; s < NS; s++) g += cw[s]*sigm(aw[s]*win[4]);
        d_g[bc*HW + h*WI + w] = g;
    }
#pragma unroll
    for (int k = 0; k < 8; k++) {
        float v = val[k];
#pragma unroll
        for (int o = 16; o > 0; o >>= 1) v += __shfl_xor_sync(0xffffffffu, v, o);
        if ((tid & 31) == 0) atomicAdd(&d_Z[bc*8+k], v);
    }
    if (inq) {
#pragma unroll
        for (int k = 0; k < 8; k++) {
            float v = val[k];
            u16 hh = f2bf(v), ll = f2bf(v - bf2f(hh));
            d_snhl[(bc*8+k)*PLANE + q] = (u32)hh | ((u32)ll << 16);
        }
    }
}

// ---------------- K2: S GEMM on tensor cores via mma.sync (HMMA) ----------------
// C[128][144] = A(x split-bf16, 128 rows) . B(tap-shifted sn, 144 rows, hi+lo)^T over K pixels.
// 9 warps: warp w owns n-tiles {2w, 2w+1}; loops 8 m-tiles; acc fp32 64 regs.
#define SM_A    0
#define SM_BH   16384
#define SM_BL   34816
#define SM_LUT  53248
#define SM_INV  53824
#define KS_SMEM 53888
__global__ __launch_bounds__(288, 2) void k_S(const float* __restrict__ x,
                                              const float* __restrict__ Wcs) {
    extern __shared__ char sm[];
    int*   sLUT = (int*)(sm + SM_LUT);
    float* sInv = (float*)(sm + SM_INV);
    u32 smb = smem_to_u32(sm);
    int tid = threadIdx.x, lane = tid & 31, w = tid >> 5;   // w: 0..8
    int kid = blockIdx.x, b = blockIdx.y;

    if (tid < 144) {
        int m = tid/9, t9 = tid%9;
        sLUT[tid] = (b*16 + m)*PLANE + 256 + (t9/3 - 1)*194 + (t9%3 - 1);
    }
    if (tid < 16) sInv[tid] = Wcs[tid & 7] / d_Z[b*16 + tid];

    // ldmatrix lane->address precompute (A row-major m16xk16; B non-trans n8xk16 rows)
    int aRow = lane & 15;                    // + mt*16
    u32 swA   = (u32)((aRow & 7) * 16);
    u32 aKo   = (u32)((lane >> 4) * 16);     // k-segment 0/1
    u32 aBase = smb + SM_A + aRow*128;
    int bRow  = w*16 + (lane >> 4)*8 + (lane & 7);   // n-tile pair rows 16w..16w+15
    u32 swB   = (u32)((lane & 7) * 16);
    u32 bKo   = (u32)(((lane >> 3) & 1) * 16);
    u32 bBaseH = smb + SM_BH + bRow*128;
    u32 bBaseL = smb + SM_BL + bRow*128;

    float acc[8][2][4];
#pragma unroll
    for (int i = 0; i < 8; i++)
#pragma unroll
        for (int j = 0; j < 2; j++)
#pragma unroll
            for (int e = 0; e < 4; e++) acc[i][j][e] = 0.f;

    int t0 = kid*TPC, ntile = NTILES - t0; if (ntile > TPC) ntile = TPC;
    const float* xb = x + (size_t)b*CH*HW;

    for (int t = 0; t < ntile; t++) {
        int p0 = (t0 + t)*64;
        __syncthreads();
        // stage A: 64ch x 64px, bf16 split into rows ch (hi) / ch+64 (lo)
        for (int idx = tid; idx < 4096; idx += 288) {
            int px = idx & 63, ch = idx >> 6;
            int p = p0 + px, hp = p/194, wp = p - hp*194;
            bool valid = (hp >= 1 && hp <= 192 && wp >= 1 && wp <= 192);
            float v = valid ? __ldg(xb + ch*HW + (hp-1)*WI + (wp-1)) : 0.f;
            u16 hh = f2bf(v), ll = f2bf(v - bf2f(hh));
            *(u16*)(sm + SM_A + SWZ(ch*128 + px*2)) = hh;
            *(u16*)(sm + SM_A + SWZ((ch+64)*128 + px*2)) = ll;
        }
        // stage B: 144 tap-shifted rows x 64px (hi and lo planes)
        for (int idx = tid; idx < 9216; idx += 288) {
            int px = idx & 63, row = idx >> 6;
            u32 hl = __ldg(&d_snhl[sLUT[row] + p0 + px]);
            u32 so = SWZ(row*128 + px*2);
            *(u16*)(sm + SM_BH + so) = (u16)hl;
            *(u16*)(sm + SM_BL + so) = (u16)(hl >> 16);
        }
        __syncthreads();
#pragma unroll
        for (int kc = 0; kc < 4; kc++) {
            u32 v = kc*32;
            u32 bh0,bh1,bh2,bh3, bl0,bl1,bl2,bl3;
            ldm4(bh0,bh1,bh2,bh3, bBaseH + ((v + bKo) ^ swB));
            ldm4(bl0,bl1,bl2,bl3, bBaseL + ((v + bKo) ^ swB));
#pragma unroll
            for (int mt = 0; mt < 8; mt++) {
                u32 a0,a1,a2,a3;
                ldm4(a0,a1,a2,a3, aBase + mt*2048 + ((v + aKo) ^ swA));
                mma_bf16(acc[mt][0], a0,a1,a2,a3, bh0,bh1);
                mma_bf16(acc[mt][1], a0,a1,a2,a3, bh2,bh3);
                mma_bf16(acc[mt][0], a0,a1,a2,a3, bl0,bl1);
                mma_bf16(acc[mt][1], a0,a1,a2,a3, bl2,bl3);
            }
        }
    }
    // epilogue: scale by Wcs/Z, fold hi(ch)+lo(ch+64) rows via atomicAdd, tap-reverse
    int r = lane >> 2, cp = (lane & 3)*2;
#pragma unroll
    for (int mt = 0; mt < 8; mt++)
#pragma unroll
        for (int j = 0; j < 2; j++) {
            int nt2 = 2*w + j;
#pragma unroll
            for (int e = 0; e < 4; e++) {
                int ch = (mt*16 + r + ((e >> 1) << 3)) & 63;
                int n  = nt2*8 + cp + (e & 1);
                int m = n/9, t9 = n - m*9;
                atomicAdd(&d_S[(b*16 + m)*576 + ch*9 + (8 - t9)], acc[mt][j][e]*sInv[m]);
            }
        }
}

// ---------------- K3: tok2 (K-quarter split) ----------------
__global__ void k_tok(const float* __restrict__ Wx) {
    __shared__ alignas(16) float Ss[144];
    int bcs = blockIdx.x, qc = blockIdx.y;
    int tid = threadIdx.x;                  // 64 = d
    for (int i = tid; i < 144; i += 64) Ss[i] = d_S[bcs*576 + qc*144 + i];
    __syncthreads();
    int s = bcs & 7;
    const float4* wr = (const float4*)(Wx + (s*64 + tid)*576 + qc*144);
    const float4* sr = (const float4*)Ss;
    float a0 = 0.f, a1 = 0.f, a2 = 0.f, a3 = 0.f;
#pragma unroll
    for (int j = 0; j < 36; j++) {
        float4 wv = wr[j], sv = sr[j];
        a0 += wv.x*sv.x; a1 += wv.y*sv.y; a2 += wv.z*sv.z; a3 += wv.w*sv.w;
    }
    atomicAdd(&d_tok2[(bcs >> 3)*64 + tid], (a0 + a1) + (a2 + a3));
}

// ---------------- K4: M2 pairs ----------------
__global__ void k_M(const float* __restrict__ Ws) {
    __shared__ float t2[128];
    int b = blockIdx.x, kk = blockIdx.y;    // 8 x 9
    int tid = threadIdx.x;                  // 128
    t2[tid] = d_tok2[b*128 + tid];
    __syncthreads();
    int o = tid & 63, c = tid >> 6;
    const float* wp = Ws + o*576 + kk;
    const float* tp = t2 + c*64;
    float a = 0.f;
#pragma unroll 8
    for (int i = 0; i < 64; i++) a += wp[i*9]*tp[i];
    ((float*)d_M2)[((b*32 + (o>>1))*20 + c*9 + kk)*2 + (o & 1)] = a;
}

// ---------------- K5: BN stats (FFMA2) ----------------
__global__ __launch_bounds__(256) void k_stats() {
    __shared__ alignas(16) ull g2[2*10*200];
    __shared__ float4 redv[256];
    int band = blockIdx.x, b = blockIdx.y;
    int tid = threadIdx.x;
    int op = tid & 31, cg = tid >> 5;
    for (int idx = tid; idx < 2*10*194; idx += 256) {
        int c = idx/1940, rem = idx%1940, r = rem/194, cc = rem%194;
        int gr = band*8 - 1 + r, gc = cc - 1;
        float v = 0.f;
        if (gr >= 0 && gr < H && gc >= 0 && gc < WI) v = d_g[(b*2 + c)*HW + gr*WI + gc];
        g2[c*2000 + r*200 + cc] = pack2(v, v);
    }
    ull m2[18];
#pragma unroll
    for (int k = 0; k < 18; k++) m2[k] = d_M2[(b*32 + op)*20 + k];
    __syncthreads();
    ull s2 = 0ull, q2 = 0ull;
    for (int r = 0; r < 8; r++) {
#pragma unroll
        for (int jt = 0; jt < 6; jt++) {
            int j = cg*24 + jt*4;
            ull wd[2][3][6];
#pragma unroll
            for (int c = 0; c < 2; c++)
#pragma unroll
                for (int u = 0; u < 3; u++) {
                    const ulonglong2* gp = (const ulonglong2*)&g2[c*2000 + (r+u)*200 + j];
                    ulonglong2 A = gp[0], Bv = gp[1], Cv = gp[2];
                    wd[c][u][0]=A.x;  wd[c][u][1]=A.y;  wd[c][u][2]=Bv.x;
                    wd[c][u][3]=Bv.y; wd[c][u][4]=Cv.x; wd[c][u][5]=Cv.y;
                }
#pragma unroll
            for (int q = 0; q < 4; q++) {
                ull y = 0ull;
#pragma unroll
                for (int c = 0; c < 2; c++)
#pragma unroll
                    for (int ky = 0; ky < 3; ky++)
#pragma unroll
                        for (int kx = 0; kx < 3; kx++)
                            ffma2(y, m2[c*9 + ky*3 + kx], wd[c][ky][q+kx]);
                fadd2(s2, y);
                ffma2(q2, y, y);
            }
        }
    }
    redv[tid] = make_float4(lo2(s2), hi2(s2), lo2(q2), hi2(q2));
    __syncthreads();
    if (tid < 32) {
        float4 a = redv[tid];
#pragma unroll
        for (int g = 1; g < 8; g++) {
            float4 t = redv[tid + 32*g];
            a.x += t.x; a.y += t.y; a.z += t.z; a.w += t.w;
        }
        atomicAdd(&d_sum[2*tid],   a.x);
        atomicAdd(&d_sum[2*tid+1], a.y);
        atomicAdd(&d_ss[2*tid],    a.z);
        atomicAdd(&d_ss[2*tid+1],  a.w);
    }
}

// ---------------- K6: out = x + relu(y0*scale + shift) ----------------
__global__ __launch_bounds__(256) void k_out(const float* __restrict__ x,
                                             float* __restrict__ out,
                                             const float* __restrict__ gamma,
                                             const float* __restrict__ beta) {
    __shared__ alignas(16) ull g2[2*10*200];
    __shared__ ull M2s[32*20];
    __shared__ float sc[64], sh[64];
    int band = blockIdx.x, b = blockIdx.y;
    int tid = threadIdx.x;
    for (int idx = tid; idx < 2*10*194; idx += 256) {
        int c = idx/1940, rem = idx%1940, r = rem/194, cc = rem%194;
        int gr = band*8 - 1 + r, gc = cc - 1;
        float v = 0.f;
        if (gr >= 0 && gr < H && gc >= 0 && gc < WI) v = d_g[(b*2 + c)*HW + gr*WI + gc];
        g2[c*2000 + r*200 + cc] = pack2(v, v);
    }
    for (int idx = tid; idx < 640; idx += 256) M2s[idx] = d_M2[b*640 + idx];
    if (tid < 64) {
        float n = (float)(B*HW);
        float mean = d_sum[tid]/n;
        float var  = d_ss[tid]/n - mean*mean;
        float s = gamma[tid]*rsqrtf(var + 1e-5f);
        sc[tid] = s;
        sh[tid] = beta[tid] - mean*s;
    }
    __syncthreads();
    for (int p = tid; p < 8*192; p += 256) {
        int r = p/192, w = p%192;
        int hh = band*8 + r;
        ull win2[18];
#pragma unroll
        for (int c = 0; c < 2; c++)
#pragma unroll
            for (int ky = 0; ky < 3; ky++)
#pragma unroll
                for (int kx = 0; kx < 3; kx++)
                    win2[c*9 + ky*3 + kx] = g2[c*2000 + (r+ky)*200 + (w+kx)];
        int base = (b*CH)*HW + hh*WI + w;
#pragma unroll 2
        for (int op = 0; op < 32; op++) {
            ull acc = 0ull;
#pragma unroll
            for (int k = 0; k < 18; k++) ffma2(acc, M2s[op*20 + k], win2[k]);
            int o0 = 2*op;
            float v0 = fmaxf(lo2(acc)*sc[o0]   + sh[o0],   0.f);
            float v1 = fmaxf(hi2(acc)*sc[o0+1] + sh[o0+1], 0.f);
            int g0 = base + o0*HW;
            out[g0]    = x[g0]    + v0;
            out[g0+HW] = x[g0+HW] + v1;
        }
    }
}

// ---------------- launch ----------------
extern "C" void kernel_launch(void* const* d_in, const int* in_sizes, int n_in,
                              void* d_out, int out_size) {
    const float* x     = (const float*)d_in[0];
    const float* score = (const float*)d_in[1];
    const float* Wk    = (const float*)d_in[2];
    const float* Wx    = (const float*)d_in[3];
    const float* Wcs   = (const float*)d_in[4];
    const float* Wcv   = (const float*)d_in[5];
    const float* Wa    = (const float*)d_in[6];
    const float* Wc    = (const float*)d_in[7];
    const float* Ws    = (const float*)d_in[8];
    const float* gamma = (const float*)d_in[9];
    const float* beta  = (const float*)d_in[10];
    float* out = (float*)d_out;

    cudaFuncSetAttribute(k_S, cudaFuncAttributeMaxDynamicSharedMemorySize, KS_SMEM);

    k_zero<<<288, 256>>>();                                   // 1
    { dim3 g(150, 16); k_pre<<<g, 256>>>(score, Wk, Wcv, Wa, Wc); }  // 2
    k_zero2<<<1, 1024>>>();                                   // 3
    { dim3 g(37, 8);   k_S<<<g, 288, KS_SMEM>>>(x, Wcs); }    // 4  <- profiled launch
    { dim3 g(128, 4);  k_tok<<<g, 64>>>(Wx); }                // 5
    { dim3 g(8, 9);    k_M<<<g, 128>>>(Ws); }                 // 6
    { dim3 g(24, 8);   k_stats<<<g, 256>>>(); }               // 7
    { dim3 g(24, 8);   k_out<<<g, 256>>>(x, out, gamma, beta); } // 8
}

// round 15
// speedup vs baseline: 1.5304x; 1.5304x over previous
#include <cuda_runtime.h>
#include <cstdint>
typedef unsigned long long ull;
typedef unsigned u32;
typedef unsigned short u16;

#define B   8
#define NC  2
#define NS  8
#define CH  64
#define H   192
#define WI  192
#define HW  (H*WI)
#define PP     37636
#define NTILES 589
#define PPK    (NTILES*64)
#define PLANE  (PPK + 512)
#define TPC    16

__device__ float d_g[B*NC*HW];
__device__ u32   d_snhl[B*16*PLANE];
__device__ float d_Z[B*NC*NS];
__device__ float d_S[B*16*576];
__device__ float d_tok2[B*NC*CH];
__device__ ull   d_M2[B*32*20];
__device__ float d_sum[CH];
__device__ float d_ss[CH];

__device__ __forceinline__ float sigm(float x){ return 1.f/(1.f+__expf(-x)); }
__device__ __forceinline__ void ffma2(ull& d, ull a, ull b){
    asm("fma.rn.f32x2 %0, %1, %2, %0;" : "+l"(d) : "l"(a), "l"(b));
}
__device__ __forceinline__ void fadd2(ull& d, ull a){
    asm("add.rn.f32x2 %0, %0, %1;" : "+l"(d) : "l"(a));
}
__device__ __forceinline__ ull pack2(float lo, float hi){
    ull r; asm("mov.b64 %0, {%1,%2};" : "=l"(r) : "f"(lo), "f"(hi)); return r;
}
__device__ __forceinline__ float lo2(ull v){ return __uint_as_float((unsigned)v); }
__device__ __forceinline__ float hi2(ull v){ return __uint_as_float((unsigned)(v>>32)); }
__device__ __forceinline__ u16 f2bf(float v){
    u16 r; asm("cvt.rn.bf16.f32 %0, %1;" : "=h"(r) : "f"(v)); return r;
}
__device__ __forceinline__ float bf2f(u16 u){
    float r; asm("cvt.f32.bf16 %0, %1;" : "=f"(r) : "h"(u)); return r;
}
__device__ __forceinline__ u32 smem_to_u32(const void* p){
    u32 a; asm("{ .reg .u64 t; cvta.to.shared.u64 t, %1; cvt.u32.u64 %0, t; }" : "=r"(a) : "l"(p)); return a;
}

__device__ __forceinline__ void ldm4(u32& r0, u32& r1, u32& r2, u32& r3, u32 addr){
    asm volatile("ldmatrix.sync.aligned.m8n8.x4.shared.b16 {%0,%1,%2,%3}, [%4];"
        : "=r"(r0),"=r"(r1),"=r"(r2),"=r"(r3) : "r"(addr));
}
__device__ __forceinline__ void mma_bf16(float (&c)[4], u32 a0,u32 a1,u32 a2,u32 a3, u32 b0,u32 b1){
    asm volatile("mma.sync.aligned.m16n8k16.row.col.f32.bf16.bf16.f32 "
        "{%0,%1,%2,%3}, {%4,%5,%6,%7}, {%8,%9}, {%0,%1,%2,%3};"
        : "+f"(c[0]),"+f"(c[1]),"+f"(c[2]),"+f"(c[3])
        : "r"(a0),"r"(a1),"r"(a2),"r"(a3),"r"(b0),"r"(b1));
}
__device__ __forceinline__ void cpa4(u32 dst, const u32* src){
    asm volatile("cp.async.ca.shared.global [%0], [%1], 4;" :: "r"(dst), "l"(src));
}

// ---------------- K0a / K0b ----------------
__global__ void k_zero() {
    int i = blockIdx.x*256 + threadIdx.x;   // 288*256 = 73728 = B*16*576
    d_S[i] = 0.f;
    if (i < B*NC*NS) d_Z[i] = 0.f;
}
__global__ void k_zero2() {
    int i = threadIdx.x;
    if (i < B*NC*CH) d_tok2[i] = 0.f;
    if (i < CH) { d_sum[i] = 0.f; d_ss[i] = 0.f; }
}

// ---------------- K1: padded split-bf16 space maps + Z + g ----------------
__global__ void k_pre(const float* __restrict__ score, const float* __restrict__ Wk,
                      const float* __restrict__ Wcv, const float* __restrict__ Wa,
                      const float* __restrict__ Wc) {
    __shared__ float wk[63], cw[8], aw[8];
    int tid = threadIdx.x;
    if (tid < 63) wk[tid] = Wk[tid];
    if (tid < 8) { cw[tid] = Wc[tid]*Wcv[tid]; aw[tid] = Wa[tid]; }
    __syncthreads();
    int bc = blockIdx.y;
    int q = blockIdx.x*256 + tid;
    float val[8];
#pragma unroll
    for (int k = 0; k < 8; k++) val[k] = 0.f;
    bool inq = (q < PLANE);
    int p = q - 256;
    bool inimg = false; int h = 0, w = 0;
    if (inq && p >= 0 && p < PP) {
        int hp = p/194, wp = p - hp*194;
        if (hp >= 1 && hp <= 192 && wp >= 1 && wp <= 192) { inimg = true; h = hp-1; w = wp-1; }
    }
    if (inimg) {
        const float* sc = score + bc*HW;
        float win[9];
#pragma unroll
        for (int u = 0; u < 3; u++)
#pragma unroll
            for (int v = 0; v < 3; v++) {
                int hh = h+u-1, ww = w+v-1;
                win[u*3+v] = (hh>=0 && hh<H && ww>=0 && ww<WI) ? sigm(sc[hh*WI+ww]) : 0.f;
            }
        val[0] = win[4];
#pragma unroll
        for (int k = 0; k < 7; k++) {
            float a = 0.f;
#pragma unroll
            for (int j = 0; j < 9; j++) a += wk[k*9+j]*win[j];
            val[k+1] = sigm(a);
        }
        float g = 0.f;
#pragma unroll
        for (int s = 0; s < NS; s++) g += cw[s]*sigm(aw[s]*win[4]);
        d_g[bc*HW + h*WI + w] = g;
    }
#pragma unroll
    for (int k = 0; k < 8; k++) {
        float v = val[k];
#pragma unroll
        for (int o = 16; o > 0; o >>= 1) v += __shfl_xor_sync(0xffffffffu, v, o);
        if ((tid & 31) == 0) atomicAdd(&d_Z[bc*8+k], v);
    }
    if (inq) {
#pragma unroll
        for (int k = 0; k < 8; k++) {
            float v = val[k];
            u16 hh = f2bf(v), ll = f2bf(v - bf2f(hh));
            d_snhl[(bc*8+k)*PLANE + q] = (u32)hh | ((u32)ll << 16);
        }
    }
}

// ---------------- K2: S GEMM, interleaved hi/lo K, double-buffered cp.async ----------------
// A[128 rows]: rows 0-63 = (xh,xh) pairs, rows 64-127 = (xl,xl). B[144 rows] = packed (snh,snl).
// Row = 64 u32 = 256B = 16 chunks of 16B, swizzle chunk ^= (row & 15).
#define ABUF(d)  ((d)*69632)
#define BBUF(d)  ((d)*69632 + 32768)
#define SM_LUT   139264
#define SM_INV   139840
#define KS_SMEM  139904
__global__ __launch_bounds__(288) void k_S(const float* __restrict__ x,
                                           const float* __restrict__ Wcs) {
    extern __shared__ char sm[];
    int*   sLUT = (int*)(sm + SM_LUT);
    float* sInv = (float*)(sm + SM_INV);
    u32 smb = smem_to_u32(sm);
    int tid = threadIdx.x, lane = tid & 31, w = tid >> 5;   // 9 warps
    int kid = blockIdx.x, b = blockIdx.y;

    if (tid < 144) {
        int m = tid/9, t9 = tid%9;
        sLUT[tid] = (b*16 + m)*PLANE + 256 + (t9/3 - 1)*194 + (t9%3 - 1);
    }
    if (tid < 16) sInv[tid] = Wcs[tid & 7] / d_Z[b*16 + tid];
    __syncthreads();

    int aRow = lane & 15;
    u32 aHalf = (u32)(lane >> 4);
    int bRow = w*16 + (lane >> 4)*8 + (lane & 7);
    u32 bHalf = (u32)((lane >> 3) & 1);
    u32 bSw = (u32)(bRow & 15);

    float acc[8][2][4];
#pragma unroll
    for (int i = 0; i < 8; i++)
#pragma unroll
        for (int j = 0; j < 2; j++)
#pragma unroll
            for (int e = 0; e < 4; e++) acc[i][j][e] = 0.f;

    int t0 = kid*TPC, nt = NTILES - t0; if (nt > TPC) nt = TPC;
    const float* xb = x + (size_t)b*CH*HW;

    float pa[15];

    // ---- prolog: stage tile 0 into buf 0 ----
    {
        int p0 = t0*64;
#pragma unroll
        for (int i = 0; i < 15; i++) {
            int idx = tid + i*288;
            if (idx < 4096) {
                int px = idx & 63, ch = idx >> 6;
                int p = p0 + px, hp = p/194, wp = p - hp*194;
                bool valid = (hp >= 1 && hp <= 192 && wp >= 1 && wp <= 192);
                pa[i] = valid ? __ldg(xb + ch*HW + (hp-1)*WI + (wp-1)) : 0.f;
            }
        }
#pragma unroll
        for (int i = 0; i < 15; i++) {
            int idx = tid + i*288;
            if (idx < 4096) {
                int px = idx & 63, ch = idx >> 6;
                float v = pa[i];
                u16 hh = f2bf(v), ll = f2bf(v - bf2f(hh));
                u32 so = (u32)(ch*256 + (((px>>2) ^ (ch & 15)) << 4) + (px & 3)*4);
                *(u32*)(sm + ABUF(0) + so) = (u32)hh * 0x10001u;
                *(u32*)(sm + ABUF(0) + 16384 + so) = (u32)ll * 0x10001u;  // rows +64: (ch+64)&15 == ch&15
            }
        }
        for (int idx = tid; idx < 9216; idx += 288) {
            int px = idx & 63, row = idx >> 6;
            const u32* src = d_snhl + sLUT[row] + p0 + px;
            u32 dst = smb + BBUF(0) + row*256 + (((px>>2) ^ (row & 15)) << 4) + (px & 3)*4;
            cpa4(dst, src);
        }
        asm volatile("cp.async.commit_group;" ::: "memory");
    }

    int d = 0;
    for (int t = 0; t < nt; t++) {
        bool more = (t + 1 < nt);
        if (more) {
            int p0n = (t0 + t + 1)*64;
#pragma unroll
            for (int i = 0; i < 15; i++) {
                int idx = tid + i*288;
                if (idx < 4096) {
                    int px = idx & 63, ch = idx >> 6;
                    int p = p0n + px, hp = p/194, wp = p - hp*194;
                    bool valid = (hp >= 1 && hp <= 192 && wp >= 1 && wp <= 192);
                    pa[i] = valid ? __ldg(xb + ch*HW + (hp-1)*WI + (wp-1)) : 0.f;
                }
            }
            for (int idx = tid; idx < 9216; idx += 288) {
                int px = idx & 63, row = idx >> 6;
                const u32* src = d_snhl + sLUT[row] + p0n + px;
                u32 dst = smb + BBUF(1-d) + row*256 + (((px>>2) ^ (row & 15)) << 4) + (px & 3)*4;
                cpa4(dst, src);
            }
            asm volatile("cp.async.commit_group;" ::: "memory");
            asm volatile("cp.async.wait_group 1;" ::: "memory");
        } else {
            asm volatile("cp.async.wait_group 0;" ::: "memory");
        }
        __syncthreads();

        // ---- MMA on buffer d ----
        {
            u32 aB = smb + ABUF(d) + aRow*256;
            u32 bB = smb + BBUF(d) + bRow*256;
#pragma unroll
            for (int kc = 0; kc < 8; kc++) {
                u32 b0,b1,b2,b3;
                ldm4(b0,b1,b2,b3, bB + ((((u32)(2*kc) + bHalf) ^ bSw) << 4));
#pragma unroll
                for (int mt = 0; mt < 8; mt++) {
                    u32 a0,a1,a2,a3;
                    ldm4(a0,a1,a2,a3, aB + mt*4096 + ((((u32)(2*kc) + aHalf) ^ (u32)aRow) << 4));
                    mma_bf16(acc[mt][0], a0,a1,a2,a3, b0,b1);
                    mma_bf16(acc[mt][1], a0,a1,a2,a3, b2,b3);
                }
            }
        }

        if (more) {
#pragma unroll
            for (int i = 0; i < 15; i++) {
                int idx = tid + i*288;
                if (idx < 4096) {
                    int px = idx & 63, ch = idx >> 6;
                    float v = pa[i];
                    u16 hh = f2bf(v), ll = f2bf(v - bf2f(hh));
                    u32 so = (u32)(ch*256 + (((px>>2) ^ (ch & 15)) << 4) + (px & 3)*4);
                    *(u32*)(sm + ABUF(1-d) + so) = (u32)hh * 0x10001u;
                    *(u32*)(sm + ABUF(1-d) + 16384 + so) = (u32)ll * 0x10001u;
                }
            }
        }
        __syncthreads();
        d ^= 1;
    }

    // ---- epilogue: scale, fold hi+lo rows, tap-reverse, atomic ----
    int r = lane >> 2, cp = (lane & 3)*2;
#pragma unroll
    for (int mt = 0; mt < 8; mt++)
#pragma unroll
        for (int j = 0; j < 2; j++) {
            int nt2 = 2*w + j;
#pragma unroll
            for (int e = 0; e < 4; e++) {
                int ch = (mt*16 + r + ((e >> 1) << 3)) & 63;
                int n  = nt2*8 + cp + (e & 1);
                int m = n/9, t9 = n - m*9;
                atomicAdd(&d_S[(b*16 + m)*576 + ch*9 + (8 - t9)], acc[mt][j][e]*sInv[m]);
            }
        }
}

// ---------------- K3: tok2 (K-quarter split) ----------------
__global__ void k_tok(const float* __restrict__ Wx) {
    __shared__ alignas(16) float Ss[144];
    int bcs = blockIdx.x, qc = blockIdx.y;
    int tid = threadIdx.x;                  // 64 = d
    for (int i = tid; i < 144; i += 64) Ss[i] = d_S[bcs*576 + qc*144 + i];
    __syncthreads();
    int s = bcs & 7;
    const float4* wr = (const float4*)(Wx + (s*64 + tid)*576 + qc*144);
    const float4* sr = (const float4*)Ss;
    float a0 = 0.f, a1 = 0.f, a2 = 0.f, a3 = 0.f;
#pragma unroll
    for (int j = 0; j < 36; j++) {
        float4 wv = wr[j], sv = sr[j];
        a0 += wv.x*sv.x; a1 += wv.y*sv.y; a2 += wv.z*sv.z; a3 += wv.w*sv.w;
    }
    atomicAdd(&d_tok2[(bcs >> 3)*64 + tid], (a0 + a1) + (a2 + a3));
}

// ---------------- K4: M2 pairs ----------------
__global__ void k_M(const float* __restrict__ Ws) {
    __shared__ float t2[128];
    int b = blockIdx.x, kk = blockIdx.y;    // 8 x 9
    int tid = threadIdx.x;                  // 128
    t2[tid] = d_tok2[b*128 + tid];
    __syncthreads();
    int o = tid & 63, c = tid >> 6;
    const float* wp = Ws + o*576 + kk;
    const float* tp = t2 + c*64;
    float a = 0.f;
#pragma unroll 8
    for (int i = 0; i < 64; i++) a += wp[i*9]*tp[i];
    ((float*)d_M2)[((b*32 + (o>>1))*20 + c*9 + kk)*2 + (o & 1)] = a;
}

// ---------------- K5: BN stats (FFMA2) ----------------
__global__ __launch_bounds__(256) void k_stats() {
    __shared__ alignas(16) ull g2[2*10*200];
    __shared__ float4 redv[256];
    int band = blockIdx.x, b = blockIdx.y;
    int tid = threadIdx.x;
    int op = tid & 31, cg = tid >> 5;
    for (int idx = tid; idx < 2*10*194; idx += 256) {
        int c = idx/1940, rem = idx%1940, r = rem/194, cc = rem%194;
        int gr = band*8 - 1 + r, gc = cc - 1;
        float v = 0.f;
        if (gr >= 0 && gr < H && gc >= 0 && gc < WI) v = d_g[(b*2 + c)*HW + gr*WI + gc];
        g2[c*2000 + r*200 + cc] = pack2(v, v);
    }
    ull m2[18];
#pragma unroll
    for (int k = 0; k < 18; k++) m2[k] = d_M2[(b*32 + op)*20 + k];
    __syncthreads();
    ull s2 = 0ull, q2 = 0ull;
    for (int r = 0; r < 8; r++) {
#pragma unroll
        for (int jt = 0; jt < 6; jt++) {
            int j = cg*24 + jt*4;
            ull wd[2][3][6];
#pragma unroll
            for (int c = 0; c < 2; c++)
#pragma unroll
                for (int u = 0; u < 3; u++) {
                    const ulonglong2* gp = (const ulonglong2*)&g2[c*2000 + (r+u)*200 + j];
                    ulonglong2 A = gp[0], Bv = gp[1], Cv = gp[2];
                    wd[c][u][0]=A.x;  wd[c][u][1]=A.y;  wd[c][u][2]=Bv.x;
                    wd[c][u][3]=Bv.y; wd[c][u][4]=Cv.x; wd[c][u][5]=Cv.y;
                }
#pragma unroll
            for (int q = 0; q < 4; q++) {
                ull y = 0ull;
#pragma unroll
                for (int c = 0; c < 2; c++)
#pragma unroll
                    for (int ky = 0; ky < 3; ky++)
#pragma unroll
                        for (int kx = 0; kx < 3; kx++)
                            ffma2(y, m2[c*9 + ky*3 + kx], wd[c][ky][q+kx]);
                fadd2(s2, y);
                ffma2(q2, y, y);
            }
        }
    }
    redv[tid] = make_float4(lo2(s2), hi2(s2), lo2(q2), hi2(q2));
    __syncthreads();
    if (tid < 32) {
        float4 a = redv[tid];
#pragma unroll
        for (int g = 1; g < 8; g++) {
            float4 t = redv[tid + 32*g];
            a.x += t.x; a.y += t.y; a.z += t.z; a.w += t.w;
        }
        atomicAdd(&d_sum[2*tid],   a.x);
        atomicAdd(&d_sum[2*tid+1], a.y);
        atomicAdd(&d_ss[2*tid],    a.z);
        atomicAdd(&d_ss[2*tid+1],  a.w);
    }
}

// ---------------- K6: out = x + relu(y0*scale + shift) ----------------
__global__ __launch_bounds__(256) void k_out(const float* __restrict__ x,
                                             float* __restrict__ out,
                                             const float* __restrict__ gamma,
                                             const float* __restrict__ beta) {
    __shared__ alignas(16) ull g2[2*10*200];
    __shared__ ull M2s[32*20];
    __shared__ float sc[64], sh[64];
    int band = blockIdx.x, b = blockIdx.y;
    int tid = threadIdx.x;
    for (int idx = tid; idx < 2*10*194; idx += 256) {
        int c = idx/1940, rem = idx%1940, r = rem/194, cc = rem%194;
        int gr = band*8 - 1 + r, gc = cc - 1;
        float v = 0.f;
        if (gr >= 0 && gr < H && gc >= 0 && gc < WI) v = d_g[(b*2 + c)*HW + gr*WI + gc];
        g2[c*2000 + r*200 + cc] = pack2(v, v);
    }
    for (int idx = tid; idx < 640; idx += 256) M2s[idx] = d_M2[b*640 + idx];
    if (tid < 64) {
        float n = (float)(B*HW);
        float mean = d_sum[tid]/n;
        float var  = d_ss[tid]/n - mean*mean;
        float s = gamma[tid]*rsqrtf(var + 1e-5f);
        sc[tid] = s;
        sh[tid] = beta[tid] - mean*s;
    }
    __syncthreads();
    for (int p = tid; p < 8*192; p += 256) {
        int r = p/192, w = p%192;
        int hh = band*8 + r;
        ull win2[18];
#pragma unroll
        for (int c = 0; c < 2; c++)
#pragma unroll
            for (int ky = 0; ky < 3; ky++)
#pragma unroll
                for (int kx = 0; kx < 3; kx++)
                    win2[c*9 + ky*3 + kx] = g2[c*2000 + (r+ky)*200 + (w+kx)];
        int base = (b*CH)*HW + hh*WI + w;
#pragma unroll 2
        for (int op = 0; op < 32; op++) {
            ull acc = 0ull;
#pragma unroll
            for (int k = 0; k < 18; k++) ffma2(acc, M2s[op*20 + k], win2[k]);
            int o0 = 2*op;
            float v0 = fmaxf(lo2(acc)*sc[o0]   + sh[o0],   0.f);
            float v1 = fmaxf(hi2(acc)*sc[o0+1] + sh[o0+1], 0.f);
            int g0 = base + o0*HW;
            out[g0]    = x[g0]    + v0;
            out[g0+HW] = x[g0+HW] + v1;
        }
    }
}

// ---------------- launch ----------------
extern "C" void kernel_launch(void* const* d_in, const int* in_sizes, int n_in,
                              void* d_out, int out_size) {
    const float* x     = (const float*)d_in[0];
    const float* score = (const float*)d_in[1];
    const float* Wk    = (const float*)d_in[2];
    const float* Wx    = (const float*)d_in[3];
    const float* Wcs   = (const float*)d_in[4];
    const float* Wcv   = (const float*)d_in[5];
    const float* Wa    = (const float*)d_in[6];
    const float* Wc    = (const float*)d_in[7];
    const float* Ws    = (const float*)d_in[8];
    const float* gamma = (const float*)d_in[9];
    const float* beta  = (const float*)d_in[10];
    float* out = (float*)d_out;

    cudaFuncSetAttribute(k_S, cudaFuncAttributeMaxDynamicSharedMemorySize, KS_SMEM);

    k_zero<<<288, 256>>>();                                          // 1
    { dim3 g(150, 16); k_pre<<<g, 256>>>(score, Wk, Wcv, Wa, Wc); }  // 2
    k_zero2<<<1, 1024>>>();                                          // 3
    { dim3 g(37, 8);   k_S<<<g, 288, KS_SMEM>>>(x, Wcs); }           // 4 <- profiled
    { dim3 g(128, 4);  k_tok<<<g, 64>>>(Wx); }                       // 5
    { dim3 g(8, 9);    k_M<<<g, 128>>>(Ws); }                        // 6
    { dim3 g(24, 8);   k_stats<<<g, 256>>>(); }                      // 7
    { dim3 g(24, 8);   k_out<<<g, 256>>>(x, out, gamma, beta); }     // 8
}